// round 7
// baseline (speedup 1.0000x reference)
#include <cuda_runtime.h>
#include <math.h>

#define B_DIM 64
#define C_DIM 80
#define T_DIM 16384
#define NTHREADS 512
#define NWARPS 16
#define NBIN 1024
#define CAP_G 680           // per-group candidate capacity
#define FULL 0xFFFFFFFFu

// order-preserving float <-> u32 key (for exact total-order selection)
__device__ __forceinline__ unsigned f2k(float f) {
    unsigned u = __float_as_uint(f);
    return u ^ ((unsigned)((int)u >> 31) | 0x80000000u);
}
__device__ __forceinline__ float k2f(unsigned k) {
    unsigned m = (k & 0x80000000u) ? 0x80000000u : 0xFFFFFFFFu;
    return __uint_as_float(k ^ m);
}

// value-linear bin: 1024 bins across [-4, 4]; clamped; deterministic
__device__ __forceinline__ int vbin(float f) {
    int bi = __float2int_rd(fmaf(f, 128.0f, 512.0f));
    return max(0, min(NBIN - 1, bi));
}

__global__ void __launch_bounds__(NTHREADS, 3)
statpool_kernel(const float* __restrict__ x, const int* __restrict__ lengths,
                float* __restrict__ out) {
    extern __shared__ unsigned sh[];
    unsigned* hist = sh;                 // [1024]
    unsigned* list = sh + NBIN;          // [6 * CAP_G]

    __shared__ float red_s[NWARPS], red_s2[NWARPS];
    __shared__ unsigned wtot[NWARPS], wbase[NWARPS];
    __shared__ unsigned s_k[6];          // global target ranks
    __shared__ float s_w[3];
    __shared__ int s_bin[6];             // bin holding each target
    __shared__ unsigned s_krem[6];       // rank within bin
    __shared__ int s_g[6];               // group id per target
    __shared__ int s_ubin[6];            // distinct target bins (-1 padded)
    __shared__ int s_gcnt[6];            // per-group candidate counts
    __shared__ unsigned s_keyout[6];

    const int row = blockIdx.x;
    const int b = row / C_DIM, c = row % C_DIM;
    const int n = lengths[b];
    const int tid = threadIdx.x, lane = tid & 31, warp = tid >> 5;

    for (int i = tid; i < NBIN; i += NTHREADS) hist[i] = 0u;
    if (tid < 6) { s_gcnt[tid] = 0; s_ubin[tid] = -1; }
    __syncthreads();

    // ---- pass 1: sum/sumsq + value-linear histogram (low-conflict atomics) ----
    const float4* x4 = (const float4*)(x + (size_t)row * T_DIM);
    const int nvec = (n + 3) >> 2;
    float sum = 0.f, sumsq = 0.f;
    for (int i = tid; i < nvec; i += NTHREADS) {
        float4 v = x4[i];
        const int t0 = i << 2;
        float vv[4] = {v.x, v.y, v.z, v.w};
#pragma unroll
        for (int j = 0; j < 4; ++j) {
            if (t0 + j < n) {
                float f = vv[j];
                sum += f; sumsq += f * f;
                atomicAdd(&hist[vbin(f)], 1u);
            }
        }
    }

    // ---- block reduce sums ----
#pragma unroll
    for (int o = 16; o; o >>= 1) {
        sum += __shfl_down_sync(FULL, sum, o);
        sumsq += __shfl_down_sync(FULL, sumsq, o);
    }
    if (lane == 0) { red_s[warp] = sum; red_s2[warp] = sumsq; }
    __syncthreads();

    // ---- inclusive scan of hist (in place): thread owns 2 consecutive bins ----
    unsigned b0 = hist[tid * 2], b1 = hist[tid * 2 + 1];
    unsigned loc = b0 + b1;
    unsigned inc = loc;
#pragma unroll
    for (int o = 1; o < 32; o <<= 1) {
        unsigned t = __shfl_up_sync(FULL, inc, o);
        if (lane >= o) inc += t;
    }
    if (lane == 31) wtot[warp] = inc;
    __syncthreads();

    if (warp == 0) {
        unsigned t = (lane < NWARPS) ? wtot[lane] : 0u;
        unsigned ti = t;
#pragma unroll
        for (int o = 1; o < 16; o <<= 1) {
            unsigned u = __shfl_up_sync(FULL, ti, o);
            if (lane >= o) ti += u;
        }
        if (lane < NWARPS) wbase[lane] = ti - t;
    } else if (tid == 32) {
        // mean/std + rank targets (concurrent with warp 0's base scan)
        float s = 0.f, s2 = 0.f;
#pragma unroll
        for (int w = 0; w < NWARPS; ++w) { s += red_s[w]; s2 += red_s2[w]; }
        float fn = (float)n;
        float mean = s / fn;
        float var = fmaxf(s2 / fn - mean * mean, 1e-6f);
        out[b * (5 * C_DIM) + 0 * C_DIM + c] = mean;
        out[b * (5 * C_DIM) + 1 * C_DIM + c] = sqrtf(var);
        float n1 = (float)(n - 1);
        const float qs[3] = {0.25f, 0.5f, 0.75f};
#pragma unroll
        for (int q = 0; q < 3; ++q) {
            float pos = qs[q] * n1;
            float flo = floorf(pos);
            s_k[2 * q]     = (unsigned)(int)flo;
            s_k[2 * q + 1] = (unsigned)(int)ceilf(pos);
            s_w[q] = pos - flo;
        }
    }
    __syncthreads();

    unsigned run = wbase[warp] + (inc - loc);
    run += b0; hist[tid * 2] = run;
    run += b1; hist[tid * 2 + 1] = run;
    __syncthreads();

    // ---- locate bin per target (6 threads binary search on cumsum) ----
    if (tid < 6) {
        unsigned k = s_k[tid];
        int lo = 0, hi = NBIN - 1;
        while (lo < hi) {
            int mid = (lo + hi) >> 1;
            if (hist[mid] > k) hi = mid; else lo = mid + 1;
        }
        s_bin[tid] = lo;
        s_krem[tid] = k - (lo ? hist[lo - 1] : 0u);
    }
    __syncthreads();

    // ---- dedup bins into groups (register-table based; no gmask) ----
    if (tid == 0) {
        int ng = 0;
#pragma unroll
        for (int j = 0; j < 6; ++j) {
            int p = s_bin[j];
            int g = -1;
            for (int g2 = 0; g2 < ng; ++g2) if (s_ubin[g2] == p) { g = g2; break; }
            if (g < 0) { g = ng; s_ubin[ng++] = p; }
            s_g[j] = g;
        }
    }
    __syncthreads();

    // broadcast distinct bins into registers (uniform)
    int ub[6];
#pragma unroll
    for (int g = 0; g < 6; ++g) ub[g] = s_ubin[g];

    // ---- pass 2: compaction into per-group lists. Compare chain, no LDS table ----
    for (int i = tid; i < nvec; i += NTHREADS) {
        float4 v = x4[i];
        const int t0 = i << 2;
        float vv[4] = {v.x, v.y, v.z, v.w};
#pragma unroll
        for (int j = 0; j < 4; ++j) {
            if (t0 + j < n) {
                float f = vv[j];
                int bi = vbin(f);
                int g = 0;
#pragma unroll
                for (int g2 = 0; g2 < 6; ++g2) if (bi == ub[g2]) g = g2 + 1;
                if (g) {
                    int pos = atomicAdd(&s_gcnt[g - 1], 1);
                    if (pos < CAP_G) list[(g - 1) * CAP_G + pos] = f2k(f);
                }
            }
        }
    }
    __syncthreads();

    // ---- exact selection: warp j resolves target j via 32-step key bisection ----
    if (warp < 6) {
        const int g = s_g[warp];
        const int cnt = s_gcnt[g];

        if (cnt <= CAP_G) {
            // bisection within the candidate list (rank within bin)
            const unsigned* L = list + g * CAP_G;
            const unsigned kk = s_krem[warp];
            unsigned prefix = 0u;
            for (int bit = 31; bit >= 0; --bit) {
                unsigned cand = prefix | (1u << bit);
                unsigned c2 = 0;
                for (int i2 = lane; i2 < CAP_G; i2 += 32)
                    if (i2 < cnt) c2 += (L[i2] < cand) ? 1u : 0u;
#pragma unroll
                for (int o = 16; o; o >>= 1) c2 += __shfl_down_sync(FULL, c2, o);
                c2 = __shfl_sync(FULL, c2, 0);
                if (c2 <= kk) prefix = cand;
            }
            if (lane == 0) s_keyout[warp] = prefix;
        } else {
            // adversarial fallback: bisection over the full global row
            const float* xs = (const float*)x4;
            const unsigned kglob = s_k[warp];
            unsigned prefix = 0u;
            for (int bit = 31; bit >= 0; --bit) {
                unsigned cand = prefix | (1u << bit);
                unsigned c2 = 0;
                for (int i2 = lane; i2 < T_DIM; i2 += 32)
                    if (i2 < n) c2 += (f2k(xs[i2]) < cand) ? 1u : 0u;
#pragma unroll
                for (int o = 16; o; o >>= 1) c2 += __shfl_down_sync(FULL, c2, o);
                c2 = __shfl_sync(FULL, c2, 0);
                if (c2 <= kglob) prefix = cand;
            }
            if (lane == 0) s_keyout[warp] = prefix;
        }
    }
    __syncthreads();

    // ---- quantile interpolation + writeback ----
    if (tid < 3) {
        float vlo = k2f(s_keyout[2 * tid]);
        float vhi = k2f(s_keyout[2 * tid + 1]);
        out[b * (5 * C_DIM) + (2 + tid) * C_DIM + c] = vlo + s_w[tid] * (vhi - vlo);
    }
}

extern "C" void kernel_launch(void* const* d_in, const int* in_sizes, int n_in,
                              void* d_out, int out_size) {
    const float* x;
    const int* lengths;
    if (in_sizes[0] == B_DIM) {
        lengths = (const int*)d_in[0];
        x = (const float*)d_in[1];
    } else {
        x = (const float*)d_in[0];
        lengths = (const int*)d_in[1];
    }
    float* out = (float*)d_out;

    size_t smem = (size_t)(NBIN + 6 * CAP_G) * sizeof(unsigned);  // ~20.3 KB
    cudaFuncSetAttribute(statpool_kernel,
                         cudaFuncAttributeMaxDynamicSharedMemorySize, (int)smem);
    statpool_kernel<<<B_DIM * C_DIM, NTHREADS, smem>>>(x, lengths, out);
}

// round 8
// speedup vs baseline: 2.1981x; 2.1981x over previous
#include <cuda_runtime.h>
#include <math.h>

#define B_DIM 64
#define C_DIM 80
#define T_DIM 16384
#define NTHREADS 512
#define NWARPS 16
#define NBIN 4096
#define CAP_G 680           // per-group candidate capacity (6*680 fits smem)
#define FULL 0xFFFFFFFFu

// order-preserving float <-> u32 key (for exact total-order selection)
__device__ __forceinline__ unsigned f2k(float f) {
    unsigned u = __float_as_uint(f);
    return u ^ ((unsigned)((int)u >> 31) | 0x80000000u);
}
__device__ __forceinline__ float k2f(unsigned k) {
    unsigned m = (k & 0x80000000u) ? 0x80000000u : 0xFFFFFFFFu;
    return __uint_as_float(k ^ m);
}

// value-linear bin: 4096 bins across [-4, 4]; clamped; deterministic
__device__ __forceinline__ int vbin(float f) {
    int bi = __float2int_rd(fmaf(f, 512.0f, 2048.0f));
    return max(0, min(NBIN - 1, bi));
}

__global__ void __launch_bounds__(NTHREADS, 3)
statpool_kernel(const float* __restrict__ x, const int* __restrict__ lengths,
                float* __restrict__ out) {
    extern __shared__ unsigned sh[];
    unsigned* hist = sh;                 // [4096]
    unsigned* list = sh + NBIN;          // [6 * CAP_G]

    __shared__ float red_s[NWARPS], red_s2[NWARPS];
    __shared__ unsigned wtot[NWARPS], wbase[NWARPS];
    __shared__ unsigned s_k[6];          // global target ranks
    __shared__ float s_w[3];
    __shared__ int s_bin[6];             // bin holding each target
    __shared__ unsigned s_krem[6];       // rank within bin
    __shared__ int s_g[6];               // group id per target
    __shared__ int s_ubin[6];            // distinct target bins (-1 padded)
    __shared__ int s_gcnt[6];            // per-group candidate counts
    __shared__ unsigned s_keyout[6];

    const int row = blockIdx.x;
    const int b = row / C_DIM, c = row % C_DIM;
    const int n = lengths[b];
    const int tid = threadIdx.x, lane = tid & 31, warp = tid >> 5;

    for (int i = tid; i < NBIN; i += NTHREADS) hist[i] = 0u;
    if (tid < 6) { s_gcnt[tid] = 0; s_ubin[tid] = -1; }
    __syncthreads();

    // ---- pass 1: sum/sumsq + value-linear histogram (low-conflict atomics).
    //      No warp collectives anywhere in this loop. ----
    const float4* x4 = (const float4*)(x + (size_t)row * T_DIM);
    const int nvec = (n + 3) >> 2;
    float sum = 0.f, sumsq = 0.f;
    for (int i = tid; i < nvec; i += NTHREADS) {
        float4 v = x4[i];
        const int t0 = i << 2;
        float vv[4] = {v.x, v.y, v.z, v.w};
#pragma unroll
        for (int j = 0; j < 4; ++j) {
            if (t0 + j < n) {
                float f = vv[j];
                sum += f; sumsq += f * f;
                atomicAdd(&hist[vbin(f)], 1u);
            }
        }
    }

    // ---- block reduce sums (uniform control flow) ----
#pragma unroll
    for (int o = 16; o; o >>= 1) {
        sum += __shfl_down_sync(FULL, sum, o);
        sumsq += __shfl_down_sync(FULL, sumsq, o);
    }
    if (lane == 0) { red_s[warp] = sum; red_s2[warp] = sumsq; }
    __syncthreads();

    // ---- inclusive scan of hist (in place): thread owns 8 consecutive bins ----
    unsigned vb[8], loc = 0;
#pragma unroll
    for (int d = 0; d < 8; ++d) { vb[d] = hist[tid * 8 + d]; loc += vb[d]; }
    unsigned inc = loc;
#pragma unroll
    for (int o = 1; o < 32; o <<= 1) {
        unsigned t = __shfl_up_sync(FULL, inc, o);
        if (lane >= o) inc += t;
    }
    if (lane == 31) wtot[warp] = inc;
    __syncthreads();

    if (warp == 0) {
        unsigned t = (lane < NWARPS) ? wtot[lane] : 0u;
        unsigned ti = t;
#pragma unroll
        for (int o = 1; o < 16; o <<= 1) {
            unsigned u = __shfl_up_sync(FULL, ti, o);
            if (lane >= o) ti += u;
        }
        if (lane < NWARPS) wbase[lane] = ti - t;
    } else if (tid == 32) {
        // mean/std + rank targets (concurrent with warp 0's base scan)
        float s = 0.f, s2 = 0.f;
#pragma unroll
        for (int w = 0; w < NWARPS; ++w) { s += red_s[w]; s2 += red_s2[w]; }
        float fn = (float)n;
        float mean = s / fn;
        float var = fmaxf(s2 / fn - mean * mean, 1e-6f);
        out[b * (5 * C_DIM) + 0 * C_DIM + c] = mean;
        out[b * (5 * C_DIM) + 1 * C_DIM + c] = sqrtf(var);
        float n1 = (float)(n - 1);
        const float qs[3] = {0.25f, 0.5f, 0.75f};
#pragma unroll
        for (int q = 0; q < 3; ++q) {
            float pos = qs[q] * n1;
            float flo = floorf(pos);
            s_k[2 * q]     = (unsigned)(int)flo;
            s_k[2 * q + 1] = (unsigned)(int)ceilf(pos);
            s_w[q] = pos - flo;
        }
    }
    __syncthreads();

    unsigned run = wbase[warp] + (inc - loc);
#pragma unroll
    for (int d = 0; d < 8; ++d) { run += vb[d]; hist[tid * 8 + d] = run; }
    __syncthreads();

    // ---- locate bin per target (6 threads binary search on cumsum) ----
    if (tid < 6) {
        unsigned k = s_k[tid];
        int lo = 0, hi = NBIN - 1;
        while (lo < hi) {
            int mid = (lo + hi) >> 1;
            if (hist[mid] > k) hi = mid; else lo = mid + 1;
        }
        s_bin[tid] = lo;
        s_krem[tid] = k - (lo ? hist[lo - 1] : 0u);
    }
    __syncthreads();

    // ---- dedup bins into groups ----
    if (tid == 0) {
        int ng = 0;
#pragma unroll
        for (int j = 0; j < 6; ++j) {
            int p = s_bin[j];
            int g = -1;
            for (int g2 = 0; g2 < ng; ++g2) if (s_ubin[g2] == p) { g = g2; break; }
            if (g < 0) { g = ng; s_ubin[ng++] = p; }
            s_g[j] = g;
        }
    }
    __syncthreads();

    // broadcast distinct bins into registers (uniform; -1 never matches)
    int ub[6];
#pragma unroll
    for (int g = 0; g < 6; ++g) ub[g] = s_ubin[g];

    // ---- pass 2: compaction into per-group lists. Register compare chain
    //      replaces the gmask LDS lookup (shift load from L1 to ALU). ----
    for (int i = tid; i < nvec; i += NTHREADS) {
        float4 v = x4[i];
        const int t0 = i << 2;
        float vv[4] = {v.x, v.y, v.z, v.w};
#pragma unroll
        for (int j = 0; j < 4; ++j) {
            if (t0 + j < n) {
                float f = vv[j];
                int bi = vbin(f);
                int g = 0;
#pragma unroll
                for (int g2 = 0; g2 < 6; ++g2) if (bi == ub[g2]) g = g2 + 1;
                if (g) {
                    int pos = atomicAdd(&s_gcnt[g - 1], 1);
                    if (pos < CAP_G) list[(g - 1) * CAP_G + pos] = f2k(f);
                }
            }
        }
    }
    __syncthreads();

    // ---- exact selection: warp j resolves target j ----
    if (warp < 6) {
        const int g = s_g[warp];
        const int cnt = s_gcnt[g];
        const unsigned kk = s_krem[warp];

        if (cnt <= CAP_G) {
            // stable-rank brute force over small candidate list (m ~ 13)
            const unsigned* L = list + g * CAP_G;
            const int m = cnt;
            for (int base = 0; base < m; base += 32) {
                int idx = base + lane;
                unsigned e = (idx < m) ? L[idx] : 0xFFFFFFFFu;
                unsigned cl = 0, ce = 0;
                for (int t = 0; t < m; ++t) {
                    unsigned o = L[t];          // broadcast read
                    cl += (o < e);
                    ce += (o == e && t < idx);
                }
                if (idx < m && cl + ce == kk) s_keyout[warp] = e;
            }
        } else {
            // adversarial fallback: exact 32-step key bisection over global row
            const float* xs = (const float*)x4;
            const unsigned kglob = s_k[warp];
            unsigned prefix = 0u;
            for (int bit = 31; bit >= 0; --bit) {
                unsigned cand = prefix | (1u << bit);
                unsigned c2 = 0;
                for (int i2 = lane; i2 < T_DIM; i2 += 32)
                    if (i2 < n) c2 += (f2k(xs[i2]) < cand) ? 1u : 0u;
#pragma unroll
                for (int o = 16; o; o >>= 1) c2 += __shfl_down_sync(FULL, c2, o);
                c2 = __shfl_sync(FULL, c2, 0);
                if (c2 <= kglob) prefix = cand;
            }
            if (lane == 0) s_keyout[warp] = prefix;
        }
    }
    __syncthreads();

    // ---- quantile interpolation + writeback ----
    if (tid < 3) {
        float vlo = k2f(s_keyout[2 * tid]);
        float vhi = k2f(s_keyout[2 * tid + 1]);
        out[b * (5 * C_DIM) + (2 + tid) * C_DIM + c] = vlo + s_w[tid] * (vhi - vlo);
    }
}

extern "C" void kernel_launch(void* const* d_in, const int* in_sizes, int n_in,
                              void* d_out, int out_size) {
    const float* x;
    const int* lengths;
    if (in_sizes[0] == B_DIM) {
        lengths = (const int*)d_in[0];
        x = (const float*)d_in[1];
    } else {
        x = (const float*)d_in[0];
        lengths = (const int*)d_in[1];
    }
    float* out = (float*)d_out;

    size_t smem = (size_t)(NBIN + 6 * CAP_G) * sizeof(unsigned);  // ~32.3 KB
    cudaFuncSetAttribute(statpool_kernel,
                         cudaFuncAttributeMaxDynamicSharedMemorySize, (int)smem);
    statpool_kernel<<<B_DIM * C_DIM, NTHREADS, smem>>>(x, lengths, out);
}

// round 9
// speedup vs baseline: 2.7831x; 1.2661x over previous
#include <cuda_runtime.h>
#include <math.h>

#define B_DIM 64
#define C_DIM 80
#define T_DIM 16384
#define NTHREADS 256
#define NWARPS 8
#define NBIN 4096
#define CAP_G 340           // per-group candidate capacity (expected ~13 used)
#define FULL 0xFFFFFFFFu

// order-preserving float <-> u32 key (for exact total-order selection)
__device__ __forceinline__ unsigned f2k(float f) {
    unsigned u = __float_as_uint(f);
    return u ^ ((unsigned)((int)u >> 31) | 0x80000000u);
}
__device__ __forceinline__ float k2f(unsigned k) {
    unsigned m = (k & 0x80000000u) ? 0x80000000u : 0xFFFFFFFFu;
    return __uint_as_float(k ^ m);
}

// value-linear bin: 4096 bins across [-4, 4]; clamped; deterministic
__device__ __forceinline__ int vbin(float f) {
    int bi = __float2int_rd(fmaf(f, 512.0f, 2048.0f));
    return max(0, min(NBIN - 1, bi));
}

__global__ void __launch_bounds__(NTHREADS, 8)
statpool_kernel(const float* __restrict__ x, const int* __restrict__ lengths,
                float* __restrict__ out) {
    extern __shared__ unsigned sh[];
    unsigned* hist = sh;                 // [4096]
    unsigned* list = sh + NBIN;          // [6 * CAP_G]
    unsigned char* gmask = (unsigned char*)(list + 6 * CAP_G);  // [4096]

    __shared__ float red_s[NWARPS], red_s2[NWARPS];
    __shared__ unsigned wtot[NWARPS], wbase[NWARPS];
    __shared__ unsigned s_k[6];          // global target ranks
    __shared__ float s_w[3];
    __shared__ int s_bin[6];             // bin holding each target
    __shared__ unsigned s_krem[6];       // rank within bin
    __shared__ int s_g[6];               // group id per target
    __shared__ int s_gcnt[6];            // per-group candidate counts
    __shared__ unsigned s_keyout[6];

    const int row = blockIdx.x;
    const int b = row / C_DIM, c = row % C_DIM;
    const int n = lengths[b];
    const int tid = threadIdx.x, lane = tid & 31, warp = tid >> 5;

    for (int i = tid; i < NBIN; i += NTHREADS) hist[i] = 0u;
    {   // zero gmask (1024 words)
        unsigned* gm32 = (unsigned*)gmask;
        for (int i = tid; i < NBIN / 4; i += NTHREADS) gm32[i] = 0u;
    }
    if (tid < 6) s_gcnt[tid] = 0;
    __syncthreads();

    // ---- pass 1: sum/sumsq + value-linear histogram. Full-vector body
    //      (no per-element bound checks) + tiny scalar tail. ----
    const float4* x4 = (const float4*)(x + (size_t)row * T_DIM);
    const int nfull = n >> 2;            // float4s that are entirely valid
    float sum = 0.f, sumsq = 0.f;
    for (int i = tid; i < nfull; i += NTHREADS) {
        float4 v = x4[i];
        float vv[4] = {v.x, v.y, v.z, v.w};
#pragma unroll
        for (int j = 0; j < 4; ++j) {
            float f = vv[j];
            sum += f; sumsq += f * f;
            atomicAdd(&hist[vbin(f)], 1u);
        }
    }
    if (tid == 0) {                      // tail: at most 3 elements
        const float* xs = (const float*)x4;
        for (int t = nfull << 2; t < n; ++t) {
            float f = xs[t];
            sum += f; sumsq += f * f;
            atomicAdd(&hist[vbin(f)], 1u);
        }
    }

    // ---- block reduce sums ----
#pragma unroll
    for (int o = 16; o; o >>= 1) {
        sum += __shfl_down_sync(FULL, sum, o);
        sumsq += __shfl_down_sync(FULL, sumsq, o);
    }
    if (lane == 0) { red_s[warp] = sum; red_s2[warp] = sumsq; }
    __syncthreads();

    // ---- inclusive scan of hist (in place): thread owns 16 consecutive bins ----
    unsigned vb[16], loc = 0;
#pragma unroll
    for (int d = 0; d < 16; ++d) { vb[d] = hist[tid * 16 + d]; loc += vb[d]; }
    unsigned inc = loc;
#pragma unroll
    for (int o = 1; o < 32; o <<= 1) {
        unsigned t = __shfl_up_sync(FULL, inc, o);
        if (lane >= o) inc += t;
    }
    if (lane == 31) wtot[warp] = inc;
    __syncthreads();

    if (warp == 0) {
        unsigned t = (lane < NWARPS) ? wtot[lane] : 0u;
        unsigned ti = t;
#pragma unroll
        for (int o = 1; o < NWARPS; o <<= 1) {
            unsigned u = __shfl_up_sync(FULL, ti, o);
            if (lane >= o) ti += u;
        }
        if (lane < NWARPS) wbase[lane] = ti - t;
    } else if (tid == 32) {
        // mean/std + rank targets (concurrent with warp 0's base scan)
        float s = 0.f, s2 = 0.f;
#pragma unroll
        for (int w = 0; w < NWARPS; ++w) { s += red_s[w]; s2 += red_s2[w]; }
        float fn = (float)n;
        float mean = s / fn;
        float var = fmaxf(s2 / fn - mean * mean, 1e-6f);
        out[b * (5 * C_DIM) + 0 * C_DIM + c] = mean;
        out[b * (5 * C_DIM) + 1 * C_DIM + c] = sqrtf(var);
        float n1 = (float)(n - 1);
        const float qs[3] = {0.25f, 0.5f, 0.75f};
#pragma unroll
        for (int q = 0; q < 3; ++q) {
            float pos = qs[q] * n1;
            float flo = floorf(pos);
            s_k[2 * q]     = (unsigned)(int)flo;
            s_k[2 * q + 1] = (unsigned)(int)ceilf(pos);
            s_w[q] = pos - flo;
        }
    }
    __syncthreads();

    unsigned run = wbase[warp] + (inc - loc);
#pragma unroll
    for (int d = 0; d < 16; ++d) { run += vb[d]; hist[tid * 16 + d] = run; }
    __syncthreads();

    // ---- locate bin per target (6 threads binary search on cumsum) ----
    if (tid < 6) {
        unsigned k = s_k[tid];
        int lo = 0, hi = NBIN - 1;
        while (lo < hi) {
            int mid = (lo + hi) >> 1;
            if (hist[mid] > k) hi = mid; else lo = mid + 1;
        }
        s_bin[tid] = lo;
        s_krem[tid] = k - (lo ? hist[lo - 1] : 0u);
    }
    __syncthreads();

    // ---- dedup bins into groups, fill gmask ----
    if (tid == 0) {
        int ng = 0;
        int ubin[6];
#pragma unroll
        for (int j = 0; j < 6; ++j) {
            int p = s_bin[j];
            int g = -1;
            for (int g2 = 0; g2 < ng; ++g2) if (ubin[g2] == p) { g = g2; break; }
            if (g < 0) { g = ng; ubin[ng++] = p; gmask[p] = (unsigned char)(g + 1); }
            s_g[j] = g;
        }
    }
    __syncthreads();

    // ---- pass 2: compaction into per-group lists via gmask LDS lookup ----
    for (int i = tid; i < nfull; i += NTHREADS) {
        float4 v = x4[i];
        float vv[4] = {v.x, v.y, v.z, v.w};
#pragma unroll
        for (int j = 0; j < 4; ++j) {
            float f = vv[j];
            int g = gmask[vbin(f)];
            if (g) {
                int pos = atomicAdd(&s_gcnt[g - 1], 1);
                if (pos < CAP_G) list[(g - 1) * CAP_G + pos] = f2k(f);
            }
        }
    }
    if (tid == 0) {                      // tail
        const float* xs = (const float*)x4;
        for (int t = nfull << 2; t < n; ++t) {
            float f = xs[t];
            int g = gmask[vbin(f)];
            if (g) {
                int pos = atomicAdd(&s_gcnt[g - 1], 1);
                if (pos < CAP_G) list[(g - 1) * CAP_G + pos] = f2k(f);
            }
        }
    }
    __syncthreads();

    // ---- exact selection: warp j resolves target j ----
    if (warp < 6) {
        const int g = s_g[warp];
        const int cnt = s_gcnt[g];
        const unsigned kk = s_krem[warp];

        if (cnt <= CAP_G) {
            // stable-rank brute force over small candidate list (m ~ 13)
            const unsigned* L = list + g * CAP_G;
            const int m = cnt;
            for (int base = 0; base < m; base += 32) {
                int idx = base + lane;
                unsigned e = (idx < m) ? L[idx] : 0xFFFFFFFFu;
                unsigned cl = 0, ce = 0;
                for (int t = 0; t < m; ++t) {
                    unsigned o = L[t];          // broadcast read
                    cl += (o < e);
                    ce += (o == e && t < idx);
                }
                if (idx < m && cl + ce == kk) s_keyout[warp] = e;
            }
        } else {
            // adversarial fallback: exact 32-step key bisection over global row
            const float* xs = (const float*)x4;
            const unsigned kglob = s_k[warp];
            unsigned prefix = 0u;
            for (int bit = 31; bit >= 0; --bit) {
                unsigned cand = prefix | (1u << bit);
                unsigned c2 = 0;
                for (int i2 = lane; i2 < T_DIM; i2 += 32)
                    if (i2 < n) c2 += (f2k(xs[i2]) < cand) ? 1u : 0u;
#pragma unroll
                for (int o = 16; o; o >>= 1) c2 += __shfl_down_sync(FULL, c2, o);
                c2 = __shfl_sync(FULL, c2, 0);
                if (c2 <= kglob) prefix = cand;
            }
            if (lane == 0) s_keyout[warp] = prefix;
        }
    }
    __syncthreads();

    // ---- quantile interpolation + writeback ----
    if (tid < 3) {
        float vlo = k2f(s_keyout[2 * tid]);
        float vhi = k2f(s_keyout[2 * tid + 1]);
        out[b * (5 * C_DIM) + (2 + tid) * C_DIM + c] = vlo + s_w[tid] * (vhi - vlo);
    }
}

extern "C" void kernel_launch(void* const* d_in, const int* in_sizes, int n_in,
                              void* d_out, int out_size) {
    const float* x;
    const int* lengths;
    if (in_sizes[0] == B_DIM) {
        lengths = (const int*)d_in[0];
        x = (const float*)d_in[1];
    } else {
        x = (const float*)d_in[0];
        lengths = (const int*)d_in[1];
    }
    float* out = (float*)d_out;

    // 4096*4 + 6*340*4 + 4096 bytes ≈ 28.7 KB -> 8 CTAs/SM within 228 KB
    size_t smem = (size_t)NBIN * sizeof(unsigned)
                + (size_t)6 * CAP_G * sizeof(unsigned) + NBIN;
    cudaFuncSetAttribute(statpool_kernel,
                         cudaFuncAttributeMaxDynamicSharedMemorySize, (int)smem);
    statpool_kernel<<<B_DIM * C_DIM, NTHREADS, smem>>>(x, lengths, out);
}